// round 5
// baseline (speedup 1.0000x reference)
#include <cuda_runtime.h>
#include <cstdint>

// Problem dims (fixed by the dataset)
#define M_DIM 8192
#define K_DIM 4096
#define N_DIM 11008

// GEMM tiling
#define BM 128
#define BN 256
#define BK 64                 // int8 k per tile = 64 bytes per row
#define STAGES 4
#define KTILES (K_DIM / BK)   // 64

#define ROW_PITCH 80                       // 64B data + 16B pad: conflict-free LDS
#define A_STAGE_BYTES (BM * ROW_PITCH)     // 10240
#define B_STAGE_BYTES (BN * ROW_PITCH)     // 20480
#define STAGE_BYTES (A_STAGE_BYTES + B_STAGE_BYTES)
#define SMEM_BYTES (STAGES * STAGE_BYTES)  // 122880

// Scratch (device globals: allocation-free rule)
__device__ __align__(128) int8_t g_Ai8[(size_t)M_DIM * K_DIM];  // 32 MB quantized x
__device__ __align__(128) int8_t g_Bt [(size_t)N_DIM * K_DIM]; // 45 MB W^T [N,K] int8

// ---------------- PTX helpers (baseline ISA only) ----------------
__device__ __forceinline__ uint32_t smem_u32(const void* p) {
    uint32_t a;
    asm("{ .reg .u64 t; cvta.to.shared.u64 t, %1; cvt.u32.u64 %0, t; }" : "=r"(a) : "l"(p));
    return a;
}
__device__ __forceinline__ void cp_async16(uint32_t dst, const void* src) {
    asm volatile("cp.async.cg.shared.global [%0], [%1], 16;" :: "r"(dst), "l"(src));
}
#define CP_COMMIT() asm volatile("cp.async.commit_group;" ::: "memory")
#define CP_WAIT(n)  asm volatile("cp.async.wait_group %0;" :: "n"(n) : "memory")

__device__ __forceinline__ uint32_t lds32(uint32_t addr) {
    uint32_t v;
    asm volatile("ld.shared.b32 %0, [%1];" : "=r"(v) : "r"(addr));
    return v;
}

#define MMA_S8(d, a, b0, b1) \
    asm volatile("mma.sync.aligned.m16n8k32.row.col.s32.s8.s8.s32 " \
        "{%0,%1,%2,%3}, {%4,%5,%6,%7}, {%8,%9}, {%0,%1,%2,%3};" \
        : "+r"((d)[0]), "+r"((d)[1]), "+r"((d)[2]), "+r"((d)[3]) \
        : "r"((a)[0]), "r"((a)[1]), "r"((a)[2]), "r"((a)[3]), "r"(b0), "r"(b1))

// ---------------- Kernel 1: quantize x (fp32) -> int8 packed ----------------
// Matches jnp.round(jnp.clip(x / s, -128, 127)) : IEEE div, clamp, round-half-even.
__global__ void quant_kernel(const float* __restrict__ x, const float* __restrict__ iscale) {
    const float s = __ldg(iscale);
    size_t i = (size_t)blockIdx.x * blockDim.x + threadIdx.x;  // one per 16 elems
    const float4* xp = (const float4*)x;
    uint32_t pk[4];
#pragma unroll
    for (int j = 0; j < 4; j++) {
        float4 v = xp[4 * i + j];
        int q0 = __float2int_rn(fminf(fmaxf(__fdiv_rn(v.x, s), -128.0f), 127.0f));
        int q1 = __float2int_rn(fminf(fmaxf(__fdiv_rn(v.y, s), -128.0f), 127.0f));
        int q2 = __float2int_rn(fminf(fmaxf(__fdiv_rn(v.z, s), -128.0f), 127.0f));
        int q3 = __float2int_rn(fminf(fmaxf(__fdiv_rn(v.w, s), -128.0f), 127.0f));
        pk[j] = (uint32_t)(q0 & 0xFF) | ((uint32_t)(q1 & 0xFF) << 8) |
                ((uint32_t)(q2 & 0xFF) << 16) | ((uint32_t)(q3 & 0xFF) << 24);
    }
    ((uint4*)g_Ai8)[i] = make_uint4(pk[0], pk[1], pk[2], pk[3]);
}

// ---------------- Kernel 2: transpose + narrow W[K,N] int32 -> Wt[N,K] int8 ----
// The harness materializes the int8 qweight as int32 (its only integer dtype).
// 64x64 tile: coalesced int4 loads, convert to int8, transposed smem store,
// contiguous 16B smem reads, coalesced 16B gmem writes.
__global__ void transpose_kernel(const int* __restrict__ w) {
    __shared__ __align__(16) int8_t tile8[64][80];  // [n][k], pitch 80 keeps uint4 reads aligned
    const int n0 = blockIdx.x * 64;
    const int k0 = blockIdx.y * 64;
    const int t = threadIdx.x;          // 256 threads
#pragma unroll
    for (int c = 0; c < 4; c++) {
        int idx = t + 256 * c;          // 0..1023 chunks of 4 int32
        int kk = idx >> 4;              // k row within tile (0..63)
        int nw = (idx & 15) * 4;        // n offset within tile
        int4 v = *(const int4*)(w + (size_t)(k0 + kk) * N_DIM + n0 + nw);
        tile8[nw + 0][kk] = (int8_t)v.x;
        tile8[nw + 1][kk] = (int8_t)v.y;
        tile8[nw + 2][kk] = (int8_t)v.z;
        tile8[nw + 3][kk] = (int8_t)v.w;
    }
    __syncthreads();
    {
        int nn = t >> 2;                // n row (0..63)
        int kw = (t & 3) * 16;          // k chunk
        uint4 v = *(uint4*)&tile8[nn][kw];
        *(uint4*)(g_Bt + (size_t)(n0 + nn) * K_DIM + k0 + kw) = v;
    }
}

// ---------------- Kernel 3: int8 mma.sync GEMM + fused dequant ----------------
__device__ __forceinline__ void issue_tile(uint32_t sb, int s, int kt, int tid,
                                           const int8_t* Abase, const int8_t* Bbase) {
    const uint32_t a_st = sb + s * STAGE_BYTES;
    const uint32_t b_st = a_st + A_STAGE_BYTES;
    const int8_t* Ak = Abase + kt * BK;
    const int8_t* Bk = Bbase + kt * BK;
#pragma unroll
    for (int i = 0; i < 2; i++) {       // A: 128 rows x 4 chunks = 512
        int idx = tid + 256 * i;
        int row = idx >> 2, c = idx & 3;
        cp_async16(a_st + row * ROW_PITCH + c * 16, Ak + (size_t)row * K_DIM + c * 16);
    }
#pragma unroll
    for (int i = 0; i < 4; i++) {       // B: 256 rows x 4 chunks = 1024
        int idx = tid + 256 * i;
        int row = idx >> 2, c = idx & 3;
        cp_async16(b_st + row * ROW_PITCH + c * 16, Bk + (size_t)row * K_DIM + c * 16);
    }
}

__global__ __launch_bounds__(256, 1)
void gemm_kernel(const float* __restrict__ wscale, const float* __restrict__ iscale,
                 float* __restrict__ out) {
    extern __shared__ char smem[];
    const uint32_t sb = smem_u32(smem);
    const int tid = threadIdx.x;
    const int wid = tid >> 5;
    const int lane = tid & 31;
    const int warp_m = wid & 1;         // 2 warp rows (64 m each)
    const int warp_n = wid >> 1;        // 4 warp cols (64 n each)

    // rasterization: GROUP m-tiles sweep N together for L2 reuse
    const int NT = N_DIM / BN;          // 43
    const int GROUP = 8;
    int pid = blockIdx.x;
    int width = GROUP * NT;
    int group = pid / width;
    int rem = pid - group * width;
    int mt_idx = group * GROUP + (rem % GROUP);
    int nt_idx = rem / GROUP;
    const int m0 = mt_idx * BM;
    const int n0 = nt_idx * BN;

    const int8_t* Abase = g_Ai8 + (size_t)m0 * K_DIM;
    const int8_t* Bbase = g_Bt  + (size_t)n0 * K_DIM;

    int acc[4][8][4];
#pragma unroll
    for (int i = 0; i < 4; i++)
#pragma unroll
        for (int j = 0; j < 8; j++)
#pragma unroll
            for (int k = 0; k < 4; k++) acc[i][j][k] = 0;

    // prologue: stages 0..2
    issue_tile(sb, 0, 0, tid, Abase, Bbase); CP_COMMIT();
    issue_tile(sb, 1, 1, tid, Abase, Bbase); CP_COMMIT();
    issue_tile(sb, 2, 2, tid, Abase, Bbase); CP_COMMIT();

    // Per-lane fragment base offsets (PTX mma.m16n8k32 s8 fragment tables):
    //   A a0: row = lane>>2, k bytes = 4*(lane&3)
    //   B b0: col n = lane>>2, k bytes = 4*(lane&3)
    const uint32_t a_frag_l = (uint32_t)(warp_m * 64 + (lane >> 2)) * ROW_PITCH
                            + 4u * (lane & 3);
    const uint32_t b_frag_l = (uint32_t)(warp_n * 64 + (lane >> 2)) * ROW_PITCH
                            + 4u * (lane & 3);

    for (int kt = 0; kt < KTILES; kt++) {
        CP_WAIT(2);
        __syncthreads();
        if (kt + 3 < KTILES) issue_tile(sb, (kt + 3) & (STAGES - 1), kt + 3, tid, Abase, Bbase);
        CP_COMMIT();

        const int s = kt & (STAGES - 1);
        const uint32_t a_st = sb + s * STAGE_BYTES;
        const uint32_t b_st = a_st + A_STAGE_BYTES;
#pragma unroll
        for (int ks = 0; ks < 2; ks++) {     // two k32 slices per BK=64
            uint32_t af[4][4];
#pragma unroll
            for (int mt = 0; mt < 4; mt++) { // 4 x 16-row m tiles
                uint32_t base = a_st + a_frag_l + (uint32_t)(mt * 16) * ROW_PITCH + ks * 32;
                af[mt][0] = lds32(base);                       // rows g,    k 0-15 of slice
                af[mt][1] = lds32(base + 8 * ROW_PITCH);       // rows g+8,  k 0-15
                af[mt][2] = lds32(base + 16);                  // rows g,    k 16-31
                af[mt][3] = lds32(base + 8 * ROW_PITCH + 16);  // rows g+8,  k 16-31
            }
            uint32_t bf[8][2];
#pragma unroll
            for (int nt = 0; nt < 8; nt++) { // 8 x 8-col n tiles
                uint32_t base = b_st + b_frag_l + (uint32_t)(nt * 8) * ROW_PITCH + ks * 32;
                bf[nt][0] = lds32(base);                       // n g, k 0-15 of slice
                bf[nt][1] = lds32(base + 16);                  // n g, k 16-31
            }
#pragma unroll
            for (int mt = 0; mt < 4; mt++)
#pragma unroll
                for (int nt = 0; nt < 8; nt++)
                    MMA_S8(acc[mt][nt], af[mt], bf[nt][0], bf[nt][1]);
        }
    }

    // ---- epilogue: fused dequant, fp32 stores ----
    const float sin = __ldg(iscale);
    const int m_base_g = m0 + warp_m * 64;
    const int n_base_g = n0 + warp_n * 64;
#pragma unroll
    for (int nt = 0; nt < 8; nt++) {
        const int n = n_base_g + nt * 8 + 2 * (lane & 3);
        const float w0 = sin * __ldg(wscale + n);
        const float w1 = sin * __ldg(wscale + n + 1);
#pragma unroll
        for (int mt = 0; mt < 4; mt++) {
            const int r0 = m_base_g + mt * 16 + (lane >> 2);
            float2 v0, v1;
            v0.x = (float)acc[mt][nt][0] * w0;
            v0.y = (float)acc[mt][nt][1] * w1;
            v1.x = (float)acc[mt][nt][2] * w0;
            v1.y = (float)acc[mt][nt][3] * w1;
            *(float2*)(out + (size_t)r0 * N_DIM + n) = v0;
            *(float2*)(out + (size_t)(r0 + 8) * N_DIM + n) = v1;
        }
    }
}

// ---------------- launch ----------------
extern "C" void kernel_launch(void* const* d_in, const int* in_sizes, int n_in,
                              void* d_out, int out_size) {
    (void)out_size;
    // Identify inputs by element count. NOTE: qweight arrives as int32
    // (harness supports only f32/i32/bf16 dtypes).
    const float* x  = nullptr;
    const int*   w  = nullptr;   // int32 weights!
    const float* ws = nullptr;
    const float* is = nullptr;
    const long long XE = (long long)M_DIM * K_DIM;
    const long long WE = (long long)K_DIM * N_DIM;
    for (int i = 0; i < n_in; i++) {
        long long sz = in_sizes[i];
        if (sz == XE)           x  = (const float*)d_in[i];
        else if (sz == WE)      w  = (const int*)d_in[i];
        else if (sz == N_DIM)   ws = (const float*)d_in[i];
        else if (sz == 1)       is = (const float*)d_in[i];
    }
    if (!x)  x  = (const float*)d_in[0];
    if (!w)  w  = (const int*)d_in[1];
    if (!ws) ws = (const float*)d_in[2];
    if (!is) is = (const float*)d_in[3];
    float* out = (float*)d_out;

    // 1) quantize x -> int8
    size_t qthreads = (size_t)M_DIM * K_DIM / 16;
    quant_kernel<<<(unsigned)(qthreads / 256), 256>>>(x, is);

    // 2) transpose + narrow W (int32 [K,N]) -> Wt (int8 [N,K])
    transpose_kernel<<<dim3(N_DIM / 64, K_DIM / 64), 256>>>(w);

    // 3) int8 tensor-core GEMM + fused dequant
    cudaFuncSetAttribute(gemm_kernel, cudaFuncAttributeMaxDynamicSharedMemorySize, SMEM_BYTES);
    gemm_kernel<<<(M_DIM / BM) * (N_DIM / BN), 256, SMEM_BYTES>>>(ws, is, out);
}

// round 6
// speedup vs baseline: 2.8815x; 2.8815x over previous
#include <cuda_runtime.h>
#include <cuda_fp16.h>
#include <cstdint>

// Problem dims (fixed by the dataset)
#define M_DIM 8192
#define K_DIM 4096
#define N_DIM 11008

// GEMM tiling
#define BM 128
#define BN 256
#define BK 64                 // fp16 elems per k-tile = 128 bytes per row
#define STAGES 3
#define KTILES (K_DIM / BK)   // 64

#define ROW_BYTES 128                      // 64 halves; XOR-swizzled chunks, no pad
#define A_STAGE_BYTES (BM * ROW_BYTES)     // 16384
#define B_STAGE_BYTES (BN * ROW_BYTES)     // 32768
#define STAGE_BYTES (A_STAGE_BYTES + B_STAGE_BYTES)
#define SMEM_BYTES (STAGES * STAGE_BYTES)  // 147456

// Scratch (device globals: allocation-free rule)
__device__ __align__(128) __half g_Ah [(size_t)M_DIM * K_DIM];  // 64 MB quantized x as fp16 ints
__device__ __align__(128) __half g_Bth[(size_t)N_DIM * K_DIM];  // 90 MB W^T [N,K] fp16

// ---------------- PTX helpers (baseline ISA only) ----------------
__device__ __forceinline__ uint32_t smem_u32(const void* p) {
    uint32_t a;
    asm("{ .reg .u64 t; cvta.to.shared.u64 t, %1; cvt.u32.u64 %0, t; }" : "=r"(a) : "l"(p));
    return a;
}
__device__ __forceinline__ void cp_async16(uint32_t dst, const void* src) {
    asm volatile("cp.async.cg.shared.global [%0], [%1], 16;" :: "r"(dst), "l"(src));
}
#define CP_COMMIT() asm volatile("cp.async.commit_group;" ::: "memory")
#define CP_WAIT(n)  asm volatile("cp.async.wait_group %0;" :: "n"(n) : "memory")

#define LDMX4(r, addr) \
    asm volatile("ldmatrix.sync.aligned.m8n8.x4.shared.b16 {%0,%1,%2,%3}, [%4];" \
        : "=r"((r)[0]), "=r"((r)[1]), "=r"((r)[2]), "=r"((r)[3]) : "r"(addr))

// m16n8k16 fp16 inputs, fp32 accumulate — D,A,B,C; C=D in place.
#define MMA_F16(d, a, b0, b1) \
    asm volatile("mma.sync.aligned.m16n8k16.row.col.f32.f16.f16.f32 " \
        "{%0,%1,%2,%3}, {%4,%5,%6,%7}, {%8,%9}, {%0,%1,%2,%3};" \
        : "+f"((d)[0]), "+f"((d)[1]), "+f"((d)[2]), "+f"((d)[3]) \
        : "r"((a)[0]), "r"((a)[1]), "r"((a)[2]), "r"((a)[3]), "r"(b0), "r"(b1))

// ---------------- Kernel 1: quantize x (fp32) -> fp16 integer values ----------
// Matches jnp.round(jnp.clip(x / s, -128, 127)); ints <= 128 are exact in fp16.
__global__ void quant_kernel(const float* __restrict__ x, const float* __restrict__ iscale) {
    const float s = __ldg(iscale);
    size_t i = (size_t)blockIdx.x * blockDim.x + threadIdx.x;  // one per 8 elems
    const float4* xp = (const float4*)x;
    float4 a = xp[2 * i];
    float4 b = xp[2 * i + 1];
    float v[8] = {a.x, a.y, a.z, a.w, b.x, b.y, b.z, b.w};
    uint32_t pk[4];
#pragma unroll
    for (int j = 0; j < 4; j++) {
        float q0 = rintf(fminf(fmaxf(__fdiv_rn(v[2 * j + 0], s), -128.0f), 127.0f));
        float q1 = rintf(fminf(fmaxf(__fdiv_rn(v[2 * j + 1], s), -128.0f), 127.0f));
        __half2 h = __floats2half2_rn(q0, q1);
        pk[j] = *reinterpret_cast<uint32_t*>(&h);
    }
    ((uint4*)g_Ah)[i] = make_uint4(pk[0], pk[1], pk[2], pk[3]);
}

// ---------------- Kernel 2: transpose + narrow W[K,N] int32 -> Wt[N,K] fp16 ----
__global__ void transpose_kernel(const int* __restrict__ w) {
    __shared__ __align__(16) __half tile[64][72];  // [n][k], pitch 72 halves (144B)
    const int n0 = blockIdx.x * 64;
    const int k0 = blockIdx.y * 64;
    const int t = threadIdx.x;          // 256 threads
#pragma unroll
    for (int c = 0; c < 4; c++) {
        int idx = t + 256 * c;          // 0..1023 chunks of 4 int32
        int kk = idx >> 4;              // k row within tile (0..63)
        int nw = (idx & 15) * 4;        // n offset within tile
        int4 v = *(const int4*)(w + (size_t)(k0 + kk) * N_DIM + n0 + nw);
        tile[nw + 0][kk] = __int2half_rn(v.x);
        tile[nw + 1][kk] = __int2half_rn(v.y);
        tile[nw + 2][kk] = __int2half_rn(v.z);
        tile[nw + 3][kk] = __int2half_rn(v.w);
    }
    __syncthreads();
#pragma unroll
    for (int c = 0; c < 2; c++) {
        int idx = t + 256 * c;          // 0..511: 64 rows x 8 chunks of 8 halves
        int nn = idx >> 3;
        int kc = (idx & 7) * 8;
        uint4 v = *(uint4*)&tile[nn][kc];
        *(uint4*)(g_Bth + (size_t)(n0 + nn) * K_DIM + k0 + kc) = v;
    }
}

// ---------------- Kernel 3: fp16 HMMA GEMM + fused dequant ----------------
// SMEM layout per stage: rows of 128B, 16B chunks XOR-swizzled by (row & 7).
__device__ __forceinline__ void issue_tile(uint32_t sb, int s, int kt, int tid,
                                           const __half* Abase, const __half* Bbase) {
    const uint32_t a_st = sb + s * STAGE_BYTES;
    const uint32_t b_st = a_st + A_STAGE_BYTES;
    const char* Ak = ((const char*)Abase) + kt * ROW_BYTES;
    const char* Bk = ((const char*)Bbase) + kt * ROW_BYTES;
#pragma unroll
    for (int i = 0; i < 4; i++) {       // A: 128 rows x 8 chunks = 1024
        int idx = tid + 256 * i;
        int row = idx >> 3, c = idx & 7;
        uint32_t so = (uint32_t)row * ROW_BYTES + (uint32_t)((c ^ (row & 7)) << 4);
        cp_async16(a_st + so, Ak + (size_t)row * (K_DIM * 2) + c * 16);
    }
#pragma unroll
    for (int i = 0; i < 8; i++) {       // B: 256 rows x 8 chunks = 2048
        int idx = tid + 256 * i;
        int row = idx >> 3, c = idx & 7;
        uint32_t so = (uint32_t)row * ROW_BYTES + (uint32_t)((c ^ (row & 7)) << 4);
        cp_async16(b_st + so, Bk + (size_t)row * (K_DIM * 2) + c * 16);
    }
}

__global__ __launch_bounds__(256, 1)
void gemm_kernel(const float* __restrict__ wscale, const float* __restrict__ iscale,
                 float* __restrict__ out) {
    extern __shared__ char smem[];
    const uint32_t sb = smem_u32(smem);
    const int tid = threadIdx.x;
    const int wid = tid >> 5;
    const int lane = tid & 31;
    const int warp_m = wid & 1;         // 2 warp rows (64 m each)
    const int warp_n = wid >> 1;        // 4 warp cols (64 n each)

    // rasterization: GROUP m-tiles sweep N together for L2 reuse
    const int NT = N_DIM / BN;          // 43
    const int GROUP = 8;
    int pid = blockIdx.x;
    int width = GROUP * NT;
    int group = pid / width;
    int rem = pid - group * width;
    int mt_idx = group * GROUP + (rem % GROUP);
    int nt_idx = rem / GROUP;
    const int m0 = mt_idx * BM;
    const int n0 = nt_idx * BN;

    const __half* Abase = g_Ah  + (size_t)m0 * K_DIM;
    const __half* Bbase = g_Bth + (size_t)n0 * K_DIM;

    float acc[4][8][4];
#pragma unroll
    for (int i = 0; i < 4; i++)
#pragma unroll
        for (int j = 0; j < 8; j++)
#pragma unroll
            for (int k = 0; k < 4; k++) acc[i][j][k] = 0.0f;

    // prologue: stages 0,1
    issue_tile(sb, 0, 0, tid, Abase, Bbase); CP_COMMIT();
    issue_tile(sb, 1, 1, tid, Abase, Bbase); CP_COMMIT();

    // ldmatrix per-lane addressing.
    // A x4 (per mt): rows (lane&15), chunk = 2*ks + (lane>>4), xor (lane&7):
    //   m0=rows0-7 k0-7, m1=rows8-15 k0-7, m2=rows0-7 k8-15, m3=rows8-15 k8-15
    //   -> regs a0..a3 per PTX m16n8k16 fragment table.
    // B x4 (per nq of 16 n): rows n + ((lane>>4)<<3) + (lane&7), chunk = 2*ks + ((lane>>3)&1):
    //   m0=n0-7 k0-7 (b0 even nt), m1=n0-7 k8-15 (b1 even), m2/m3 = odd nt.
    const int lw = lane & 7;
    const uint32_t a_row_off = (uint32_t)(warp_m * 64 + (lane & 15)) * ROW_BYTES;
    const uint32_t b_row_off = (uint32_t)(warp_n * 64 + ((lane >> 4) << 3) + (lane & 7)) * ROW_BYTES;
    const int a_hi = lane >> 4;          // 0..1
    const int b_hi = (lane >> 3) & 1;    // 0..1
    uint32_t a_ck[4], b_ck[4];
#pragma unroll
    for (int ks = 0; ks < 4; ks++) {
        a_ck[ks] = (uint32_t)(((2 * ks + a_hi) ^ lw) << 4);
        b_ck[ks] = (uint32_t)(((2 * ks + b_hi) ^ lw) << 4);
    }

    for (int kt = 0; kt < KTILES; kt++) {
        CP_WAIT(1);
        __syncthreads();
        if (kt + 2 < KTILES) issue_tile(sb, (kt + 2) % STAGES, kt + 2, tid, Abase, Bbase);
        CP_COMMIT();

        const int s = kt % STAGES;
        const uint32_t a_st = sb + s * STAGE_BYTES;
        const uint32_t b_st = a_st + A_STAGE_BYTES;
#pragma unroll
        for (int ks = 0; ks < 4; ks++) {   // four k16 slices per BK=64
            uint32_t af[4][4], bf[4][4];
#pragma unroll
            for (int mt = 0; mt < 4; mt++)
                LDMX4(af[mt], a_st + a_row_off + (uint32_t)(mt * 16) * ROW_BYTES + a_ck[ks]);
#pragma unroll
            for (int nq = 0; nq < 4; nq++)
                LDMX4(bf[nq], b_st + b_row_off + (uint32_t)(nq * 16) * ROW_BYTES + b_ck[ks]);
#pragma unroll
            for (int mt = 0; mt < 4; mt++)
#pragma unroll
                for (int nt = 0; nt < 8; nt++)
                    MMA_F16(acc[mt][nt], af[mt],
                            bf[nt >> 1][(nt & 1) * 2], bf[nt >> 1][(nt & 1) * 2 + 1]);
        }
    }

    // ---- epilogue: fused dequant, fp32 stores ----
    const float sin = __ldg(iscale);
    const int m_base_g = m0 + warp_m * 64;
    const int n_base_g = n0 + warp_n * 64;
#pragma unroll
    for (int nt = 0; nt < 8; nt++) {
        const int n = n_base_g + nt * 8 + 2 * (lane & 3);
        const float w0 = sin * __ldg(wscale + n);
        const float w1 = sin * __ldg(wscale + n + 1);
#pragma unroll
        for (int mt = 0; mt < 4; mt++) {
            const int r0 = m_base_g + mt * 16 + (lane >> 2);
            float2 v0, v1;
            v0.x = acc[mt][nt][0] * w0;
            v0.y = acc[mt][nt][1] * w1;
            v1.x = acc[mt][nt][2] * w0;
            v1.y = acc[mt][nt][3] * w1;
            *(float2*)(out + (size_t)r0 * N_DIM + n) = v0;
            *(float2*)(out + (size_t)(r0 + 8) * N_DIM + n) = v1;
        }
    }
}

// ---------------- launch ----------------
extern "C" void kernel_launch(void* const* d_in, const int* in_sizes, int n_in,
                              void* d_out, int out_size) {
    (void)out_size;
    // Inputs identified by element count; qweight arrives as int32.
    const float* x  = nullptr;
    const int*   w  = nullptr;
    const float* ws = nullptr;
    const float* is = nullptr;
    const long long XE = (long long)M_DIM * K_DIM;
    const long long WE = (long long)K_DIM * N_DIM;
    for (int i = 0; i < n_in; i++) {
        long long sz = in_sizes[i];
        if (sz == XE)           x  = (const float*)d_in[i];
        else if (sz == WE)      w  = (const int*)d_in[i];
        else if (sz == N_DIM)   ws = (const float*)d_in[i];
        else if (sz == 1)       is = (const float*)d_in[i];
    }
    if (!x)  x  = (const float*)d_in[0];
    if (!w)  w  = (const int*)d_in[1];
    if (!ws) ws = (const float*)d_in[2];
    if (!is) is = (const float*)d_in[3];
    float* out = (float*)d_out;

    // 1) quantize x -> fp16 ints
    size_t qthreads = (size_t)M_DIM * K_DIM / 8;
    quant_kernel<<<(unsigned)(qthreads / 256), 256>>>(x, is);

    // 2) transpose + narrow W (int32 [K,N]) -> Wt (fp16 [N,K])
    transpose_kernel<<<dim3(N_DIM / 64, K_DIM / 64), 256>>>(w);

    // 3) fp16 tensor-core GEMM + fused dequant
    cudaFuncSetAttribute(gemm_kernel, cudaFuncAttributeMaxDynamicSharedMemorySize, SMEM_BYTES);
    gemm_kernel<<<(M_DIM / BM) * (N_DIM / BN), 256, SMEM_BYTES>>>(ws, is, out);
}

// round 7
// speedup vs baseline: 3.0529x; 1.0595x over previous
#include <cuda_runtime.h>
#include <cuda_fp16.h>
#include <cstdint>

// Problem dims (fixed by the dataset)
#define M_DIM 8192
#define K_DIM 4096
#define N_DIM 11008

// GEMM tiling
#define BM 128
#define BN 256
#define BK 64                 // fp16 elems per k-tile = 128 bytes per row
#define STAGES 4
#define KTILES (K_DIM / BK)   // 64
#define NTHREADS 512

#define ROW_BYTES 128                      // 64 halves; XOR-swizzled chunks, no pad
#define A_STAGE_BYTES (BM * ROW_BYTES)     // 16384
#define B_STAGE_BYTES (BN * ROW_BYTES)     // 32768
#define STAGE_BYTES (A_STAGE_BYTES + B_STAGE_BYTES)
#define SMEM_BYTES (STAGES * STAGE_BYTES)  // 196608

// Scratch (device globals: allocation-free rule)
__device__ __align__(128) __half g_Ah [(size_t)M_DIM * K_DIM];  // 64 MB quantized x as fp16 ints
__device__ __align__(128) __half g_Bth[(size_t)N_DIM * K_DIM];  // 90 MB W^T [N,K] fp16

// ---------------- PTX helpers (baseline ISA only) ----------------
__device__ __forceinline__ uint32_t smem_u32(const void* p) {
    uint32_t a;
    asm("{ .reg .u64 t; cvta.to.shared.u64 t, %1; cvt.u32.u64 %0, t; }" : "=r"(a) : "l"(p));
    return a;
}
__device__ __forceinline__ void cp_async16(uint32_t dst, const void* src) {
    asm volatile("cp.async.cg.shared.global [%0], [%1], 16;" :: "r"(dst), "l"(src));
}
#define CP_COMMIT() asm volatile("cp.async.commit_group;" ::: "memory")
#define CP_WAIT(n)  asm volatile("cp.async.wait_group %0;" :: "n"(n) : "memory")

#define LDMX4(r, addr) \
    asm volatile("ldmatrix.sync.aligned.m8n8.x4.shared.b16 {%0,%1,%2,%3}, [%4];" \
        : "=r"((r)[0]), "=r"((r)[1]), "=r"((r)[2]), "=r"((r)[3]) : "r"(addr))

// m16n8k16 fp16 inputs, fp32 accumulate — C=D in place.
#define MMA_F16(d, a, b0, b1) \
    asm volatile("mma.sync.aligned.m16n8k16.row.col.f32.f16.f16.f32 " \
        "{%0,%1,%2,%3}, {%4,%5,%6,%7}, {%8,%9}, {%0,%1,%2,%3};" \
        : "+f"((d)[0]), "+f"((d)[1]), "+f"((d)[2]), "+f"((d)[3]) \
        : "r"((a)[0]), "r"((a)[1]), "r"((a)[2]), "r"((a)[3]), "r"(b0), "r"(b1))

// ---------------- Kernel 1: quantize x (fp32) -> fp16 integer values ----------
// Matches jnp.round(jnp.clip(x / s, -128, 127)); ints <= 128 are exact in fp16.
__global__ void quant_kernel(const float* __restrict__ x, const float* __restrict__ iscale) {
    const float s = __ldg(iscale);
    size_t i = (size_t)blockIdx.x * blockDim.x + threadIdx.x;  // one per 8 elems
    const float4* xp = (const float4*)x;
    float4 a = xp[2 * i];
    float4 b = xp[2 * i + 1];
    float v[8] = {a.x, a.y, a.z, a.w, b.x, b.y, b.z, b.w};
    uint32_t pk[4];
#pragma unroll
    for (int j = 0; j < 4; j++) {
        float q0 = rintf(fminf(fmaxf(__fdiv_rn(v[2 * j + 0], s), -128.0f), 127.0f));
        float q1 = rintf(fminf(fmaxf(__fdiv_rn(v[2 * j + 1], s), -128.0f), 127.0f));
        __half2 h = __floats2half2_rn(q0, q1);
        pk[j] = *reinterpret_cast<uint32_t*>(&h);
    }
    ((uint4*)g_Ah)[i] = make_uint4(pk[0], pk[1], pk[2], pk[3]);
}

// ---------------- Kernel 2: transpose + narrow W[K,N] int32 -> Wt[N,K] fp16 ----
__global__ void transpose_kernel(const int* __restrict__ w) {
    __shared__ __align__(16) __half tile[64][72];  // [n][k], pitch 72 halves (144B)
    const int n0 = blockIdx.x * 64;
    const int k0 = blockIdx.y * 64;
    const int t = threadIdx.x;          // 256 threads
#pragma unroll
    for (int c = 0; c < 4; c++) {
        int idx = t + 256 * c;          // 0..1023 chunks of 4 int32
        int kk = idx >> 4;              // k row within tile (0..63)
        int nw = (idx & 15) * 4;        // n offset within tile
        int4 v = *(const int4*)(w + (size_t)(k0 + kk) * N_DIM + n0 + nw);
        tile[nw + 0][kk] = __int2half_rn(v.x);
        tile[nw + 1][kk] = __int2half_rn(v.y);
        tile[nw + 2][kk] = __int2half_rn(v.z);
        tile[nw + 3][kk] = __int2half_rn(v.w);
    }
    __syncthreads();
#pragma unroll
    for (int c = 0; c < 2; c++) {
        int idx = t + 256 * c;          // 0..511: 64 rows x 8 chunks of 8 halves
        int nn = idx >> 3;
        int kc = (idx & 7) * 8;
        uint4 v = *(uint4*)&tile[nn][kc];
        *(uint4*)(g_Bth + (size_t)(n0 + nn) * K_DIM + k0 + kc) = v;
    }
}

// ---------------- Kernel 3: fp16 HMMA GEMM + fused dequant ----------------
// SMEM per stage: rows of 128B, 16B chunks XOR-swizzled by (row & 7).
__device__ __forceinline__ void issue_tile(uint32_t sb, int s, int kt, int tid,
                                           const __half* Abase, const __half* Bbase) {
    const uint32_t a_st = sb + s * STAGE_BYTES;
    const uint32_t b_st = a_st + A_STAGE_BYTES;
    const char* Ak = ((const char*)Abase) + kt * ROW_BYTES;
    const char* Bk = ((const char*)Bbase) + kt * ROW_BYTES;
#pragma unroll
    for (int i = 0; i < 2; i++) {       // A: 128 rows x 8 chunks = 1024
        int idx = tid + NTHREADS * i;
        int row = idx >> 3, c = idx & 7;
        uint32_t so = (uint32_t)row * ROW_BYTES + (uint32_t)((c ^ (row & 7)) << 4);
        cp_async16(a_st + so, Ak + (size_t)row * (K_DIM * 2) + c * 16);
    }
#pragma unroll
    for (int i = 0; i < 4; i++) {       // B: 256 rows x 8 chunks = 2048
        int idx = tid + NTHREADS * i;
        int row = idx >> 3, c = idx & 7;
        uint32_t so = (uint32_t)row * ROW_BYTES + (uint32_t)((c ^ (row & 7)) << 4);
        cp_async16(b_st + so, Bk + (size_t)row * (K_DIM * 2) + c * 16);
    }
}

__global__ __launch_bounds__(NTHREADS, 1)
void gemm_kernel(const float* __restrict__ wscale, const float* __restrict__ iscale,
                 float* __restrict__ out) {
    extern __shared__ char smem[];
    const uint32_t sb = smem_u32(smem);
    const int tid = threadIdx.x;
    const int wid = tid >> 5;
    const int lane = tid & 31;
    const int warp_m = wid & 1;         // 2 warp rows (64 m each)
    const int warp_n = wid >> 1;        // 8 warp cols (32 n each)

    // rasterization: GROUP m-tiles sweep N together for L2 reuse
    const int NT = N_DIM / BN;          // 43
    const int GROUP = 8;
    int pid = blockIdx.x;
    int width = GROUP * NT;
    int group = pid / width;
    int rem = pid - group * width;
    int mt_idx = group * GROUP + (rem % GROUP);
    int nt_idx = rem / GROUP;
    const int m0 = mt_idx * BM;
    const int n0 = nt_idx * BN;

    const __half* Abase = g_Ah  + (size_t)m0 * K_DIM;
    const __half* Bbase = g_Bth + (size_t)n0 * K_DIM;

    float acc[4][4][4];
#pragma unroll
    for (int i = 0; i < 4; i++)
#pragma unroll
        for (int j = 0; j < 4; j++)
#pragma unroll
            for (int k = 0; k < 4; k++) acc[i][j][k] = 0.0f;

    // prologue: stages 0..2 (3 in flight)
    issue_tile(sb, 0, 0, tid, Abase, Bbase); CP_COMMIT();
    issue_tile(sb, 1, 1, tid, Abase, Bbase); CP_COMMIT();
    issue_tile(sb, 2, 2, tid, Abase, Bbase); CP_COMMIT();

    // ldmatrix per-lane addressing (PTX m16n8k16 fragment tables):
    // A x4: rows (lane&15) of the 16-row mt tile, chunk = 2*ks + (lane>>4).
    // B x4: rows n + ((lane>>4)<<3) + (lane&7) of 16-n nq tile, chunk = 2*ks + ((lane>>3)&1).
    const int lw = lane & 7;
    const uint32_t a_row_off = (uint32_t)(warp_m * 64 + (lane & 15)) * ROW_BYTES;
    const uint32_t b_row_off = (uint32_t)(warp_n * 32 + ((lane >> 4) << 3) + (lane & 7)) * ROW_BYTES;
    const int a_hi = lane >> 4;          // 0..1
    const int b_hi = (lane >> 3) & 1;    // 0..1
    uint32_t a_ck[4], b_ck[4];
#pragma unroll
    for (int ks = 0; ks < 4; ks++) {
        a_ck[ks] = (uint32_t)(((2 * ks + a_hi) ^ lw) << 4);
        b_ck[ks] = (uint32_t)(((2 * ks + b_hi) ^ lw) << 4);
    }

    for (int kt = 0; kt < KTILES; kt++) {
        CP_WAIT(2);
        __syncthreads();
        if (kt + 3 < KTILES) issue_tile(sb, (kt + 3) & (STAGES - 1), kt + 3, tid, Abase, Bbase);
        CP_COMMIT();

        const int s = kt & (STAGES - 1);
        const uint32_t a_st = sb + s * STAGE_BYTES;
        const uint32_t b_st = a_st + A_STAGE_BYTES;
#pragma unroll
        for (int ks = 0; ks < 4; ks++) {   // four k16 slices per BK=64
            uint32_t af[4][4], bf[2][4];
#pragma unroll
            for (int mt = 0; mt < 4; mt++)
                LDMX4(af[mt], a_st + a_row_off + (uint32_t)(mt * 16) * ROW_BYTES + a_ck[ks]);
#pragma unroll
            for (int nq = 0; nq < 2; nq++)
                LDMX4(bf[nq], b_st + b_row_off + (uint32_t)(nq * 16) * ROW_BYTES + b_ck[ks]);
#pragma unroll
            for (int mt = 0; mt < 4; mt++)
#pragma unroll
                for (int nt = 0; nt < 4; nt++)
                    MMA_F16(acc[mt][nt], af[mt],
                            bf[nt >> 1][(nt & 1) * 2], bf[nt >> 1][(nt & 1) * 2 + 1]);
        }
    }

    // ---- epilogue: fused dequant, fp32 stores ----
    const float sin = __ldg(iscale);
    const int m_base_g = m0 + warp_m * 64;
    const int n_base_g = n0 + warp_n * 32;
#pragma unroll
    for (int nt = 0; nt < 4; nt++) {
        const int n = n_base_g + nt * 8 + 2 * (lane & 3);
        const float w0 = sin * __ldg(wscale + n);
        const float w1 = sin * __ldg(wscale + n + 1);
#pragma unroll
        for (int mt = 0; mt < 4; mt++) {
            const int r0 = m_base_g + mt * 16 + (lane >> 2);
            float2 v0, v1;
            v0.x = acc[mt][nt][0] * w0;
            v0.y = acc[mt][nt][1] * w1;
            v1.x = acc[mt][nt][2] * w0;
            v1.y = acc[mt][nt][3] * w1;
            *(float2*)(out + (size_t)r0 * N_DIM + n) = v0;
            *(float2*)(out + (size_t)(r0 + 8) * N_DIM + n) = v1;
        }
    }
}

// ---------------- launch ----------------
extern "C" void kernel_launch(void* const* d_in, const int* in_sizes, int n_in,
                              void* d_out, int out_size) {
    (void)out_size;
    // Inputs identified by element count; qweight arrives as int32.
    const float* x  = nullptr;
    const int*   w  = nullptr;
    const float* ws = nullptr;
    const float* is = nullptr;
    const long long XE = (long long)M_DIM * K_DIM;
    const long long WE = (long long)K_DIM * N_DIM;
    for (int i = 0; i < n_in; i++) {
        long long sz = in_sizes[i];
        if (sz == XE)           x  = (const float*)d_in[i];
        else if (sz == WE)      w  = (const int*)d_in[i];
        else if (sz == N_DIM)   ws = (const float*)d_in[i];
        else if (sz == 1)       is = (const float*)d_in[i];
    }
    if (!x)  x  = (const float*)d_in[0];
    if (!w)  w  = (const int*)d_in[1];
    if (!ws) ws = (const float*)d_in[2];
    if (!is) is = (const float*)d_in[3];
    float* out = (float*)d_out;

    // 1) quantize x -> fp16 ints
    size_t qthreads = (size_t)M_DIM * K_DIM / 8;
    quant_kernel<<<(unsigned)(qthreads / 256), 256>>>(x, is);

    // 2) transpose + narrow W (int32 [K,N]) -> Wt (fp16 [N,K])
    transpose_kernel<<<dim3(N_DIM / 64, K_DIM / 64), 256>>>(w);

    // 3) fp16 tensor-core GEMM + fused dequant
    cudaFuncSetAttribute(gemm_kernel, cudaFuncAttributeMaxDynamicSharedMemorySize, SMEM_BYTES);
    gemm_kernel<<<(M_DIM / BM) * (N_DIM / BN), NTHREADS, SMEM_BYTES>>>(ws, is, out);
}

// round 8
// speedup vs baseline: 3.2395x; 1.0611x over previous
#include <cuda_runtime.h>
#include <cuda_fp16.h>
#include <cstdint>

// Problem dims (fixed by the dataset)
#define M_DIM 8192
#define K_DIM 4096
#define N_DIM 11008

// GEMM tiling
#define BM 128
#define BN 128
#define BK 64                 // fp16 elems per k-tile = 128 bytes per row
#define STAGES 3
#define KTILES (K_DIM / BK)   // 64
#define NTHREADS 256

#define ROW_BYTES 128                      // 64 halves; XOR-swizzled chunks, no pad
#define A_STAGE_BYTES (BM * ROW_BYTES)     // 16384
#define B_STAGE_BYTES (BN * ROW_BYTES)     // 16384
#define STAGE_BYTES (A_STAGE_BYTES + B_STAGE_BYTES)
#define SMEM_BYTES (STAGES * STAGE_BYTES)  // 98304 -> 2 CTAs/SM

// Scratch (device globals: allocation-free rule)
__device__ __align__(128) __half g_Ah [(size_t)M_DIM * K_DIM];  // 64 MB quantized x as fp16 ints
__device__ __align__(128) __half g_Bth[(size_t)N_DIM * K_DIM];  // 90 MB W^T [N,K] fp16

// ---------------- PTX helpers (baseline ISA only) ----------------
__device__ __forceinline__ uint32_t smem_u32(const void* p) {
    uint32_t a;
    asm("{ .reg .u64 t; cvta.to.shared.u64 t, %1; cvt.u32.u64 %0, t; }" : "=r"(a) : "l"(p));
    return a;
}
__device__ __forceinline__ void cp_async16(uint32_t dst, const void* src) {
    asm volatile("cp.async.cg.shared.global [%0], [%1], 16;" :: "r"(dst), "l"(src));
}
#define CP_COMMIT() asm volatile("cp.async.commit_group;" ::: "memory")
#define CP_WAIT(n)  asm volatile("cp.async.wait_group %0;" :: "n"(n) : "memory")

#define LDMX4(r, addr) \
    asm volatile("ldmatrix.sync.aligned.m8n8.x4.shared.b16 {%0,%1,%2,%3}, [%4];" \
        : "=r"((r)[0]), "=r"((r)[1]), "=r"((r)[2]), "=r"((r)[3]) : "r"(addr))

// m16n8k16 fp16 inputs, fp32 accumulate — C=D in place.
#define MMA_F16(d, a, b0, b1) \
    asm volatile("mma.sync.aligned.m16n8k16.row.col.f32.f16.f16.f32 " \
        "{%0,%1,%2,%3}, {%4,%5,%6,%7}, {%8,%9}, {%0,%1,%2,%3};" \
        : "+f"((d)[0]), "+f"((d)[1]), "+f"((d)[2]), "+f"((d)[3]) \
        : "r"((a)[0]), "r"((a)[1]), "r"((a)[2]), "r"((a)[3]), "r"(b0), "r"(b1))

// ---------------- Kernel 1: quantize x (fp32) -> fp16 integer values ----------
// Matches jnp.round(jnp.clip(x / s, -128, 127)); ints <= 128 are exact in fp16.
__global__ void quant_kernel(const float* __restrict__ x, const float* __restrict__ iscale) {
    const float s = __ldg(iscale);
    size_t i = (size_t)blockIdx.x * blockDim.x + threadIdx.x;  // one per 8 elems
    const float4* xp = (const float4*)x;
    float4 a = xp[2 * i];
    float4 b = xp[2 * i + 1];
    float v[8] = {a.x, a.y, a.z, a.w, b.x, b.y, b.z, b.w};
    uint32_t pk[4];
#pragma unroll
    for (int j = 0; j < 4; j++) {
        float q0 = rintf(fminf(fmaxf(__fdiv_rn(v[2 * j + 0], s), -128.0f), 127.0f));
        float q1 = rintf(fminf(fmaxf(__fdiv_rn(v[2 * j + 1], s), -128.0f), 127.0f));
        __half2 h = __floats2half2_rn(q0, q1);
        pk[j] = *reinterpret_cast<uint32_t*>(&h);
    }
    ((uint4*)g_Ah)[i] = make_uint4(pk[0], pk[1], pk[2], pk[3]);
}

// ---------------- Kernel 2: transpose + narrow W[K,N] int32 -> Wt[N,K] fp16 ----
__global__ void transpose_kernel(const int* __restrict__ w) {
    __shared__ __align__(16) __half tile[64][72];  // [n][k], pitch 72 halves (144B)
    const int n0 = blockIdx.x * 64;
    const int k0 = blockIdx.y * 64;
    const int t = threadIdx.x;          // 256 threads
#pragma unroll
    for (int c = 0; c < 4; c++) {
        int idx = t + 256 * c;          // 0..1023 chunks of 4 int32
        int kk = idx >> 4;              // k row within tile (0..63)
        int nw = (idx & 15) * 4;        // n offset within tile
        int4 v = *(const int4*)(w + (size_t)(k0 + kk) * N_DIM + n0 + nw);
        tile[nw + 0][kk] = __int2half_rn(v.x);
        tile[nw + 1][kk] = __int2half_rn(v.y);
        tile[nw + 2][kk] = __int2half_rn(v.z);
        tile[nw + 3][kk] = __int2half_rn(v.w);
    }
    __syncthreads();
#pragma unroll
    for (int c = 0; c < 2; c++) {
        int idx = t + 256 * c;          // 0..511: 64 rows x 8 chunks of 8 halves
        int nn = idx >> 3;
        int kc = (idx & 7) * 8;
        uint4 v = *(uint4*)&tile[nn][kc];
        *(uint4*)(g_Bth + (size_t)(n0 + nn) * K_DIM + k0 + kc) = v;
    }
}

// ---------------- Kernel 3: fp16 HMMA GEMM + fused dequant ----------------
// SMEM per stage: rows of 128B, 16B chunks XOR-swizzled by (row & 7).
__device__ __forceinline__ void issue_tile(uint32_t sb, int s, int kt, int tid,
                                           const __half* Abase, const __half* Bbase) {
    const uint32_t a_st = sb + s * STAGE_BYTES;
    const uint32_t b_st = a_st + A_STAGE_BYTES;
    const char* Ak = ((const char*)Abase) + kt * ROW_BYTES;
    const char* Bk = ((const char*)Bbase) + kt * ROW_BYTES;
#pragma unroll
    for (int i = 0; i < 4; i++) {       // A: 128 rows x 8 chunks = 1024
        int idx = tid + NTHREADS * i;
        int row = idx >> 3, c = idx & 7;
        uint32_t so = (uint32_t)row * ROW_BYTES + (uint32_t)((c ^ (row & 7)) << 4);
        cp_async16(a_st + so, Ak + (size_t)row * (K_DIM * 2) + c * 16);
    }
#pragma unroll
    for (int i = 0; i < 4; i++) {       // B: 128 rows x 8 chunks = 1024
        int idx = tid + NTHREADS * i;
        int row = idx >> 3, c = idx & 7;
        uint32_t so = (uint32_t)row * ROW_BYTES + (uint32_t)((c ^ (row & 7)) << 4);
        cp_async16(b_st + so, Bk + (size_t)row * (K_DIM * 2) + c * 16);
    }
}

__global__ __launch_bounds__(NTHREADS, 2)
void gemm_kernel(const float* __restrict__ wscale, const float* __restrict__ iscale,
                 float* __restrict__ out) {
    extern __shared__ char smem[];
    const uint32_t sb = smem_u32(smem);
    const int tid = threadIdx.x;
    const int wid = tid >> 5;
    const int lane = tid & 31;
    const int warp_m = wid & 1;         // 2 warp rows (64 m each)
    const int warp_n = wid >> 1;        // 4 warp cols (32 n each)

    // rasterization: GROUP m-tiles sweep N together for L2 reuse of the A band
    const int NT = N_DIM / BN;          // 86
    const int GROUP = 16;
    int pid = blockIdx.x;
    int width = GROUP * NT;
    int group = pid / width;
    int rem = pid - group * width;
    int mt_idx = group * GROUP + (rem % GROUP);
    int nt_idx = rem / GROUP;
    const int m0 = mt_idx * BM;
    const int n0 = nt_idx * BN;

    const __half* Abase = g_Ah  + (size_t)m0 * K_DIM;
    const __half* Bbase = g_Bth + (size_t)n0 * K_DIM;

    float acc[4][4][4];
#pragma unroll
    for (int i = 0; i < 4; i++)
#pragma unroll
        for (int j = 0; j < 4; j++)
#pragma unroll
            for (int k = 0; k < 4; k++) acc[i][j][k] = 0.0f;

    // prologue: stages 0,1 in flight
    issue_tile(sb, 0, 0, tid, Abase, Bbase); CP_COMMIT();
    issue_tile(sb, 1, 1, tid, Abase, Bbase); CP_COMMIT();

    // ldmatrix per-lane addressing (PTX m16n8k16 fragment tables):
    // A x4: rows (lane&15) of the 16-row mt tile, chunk = 2*ks + (lane>>4).
    // B x4: rows n + ((lane>>4)<<3) + (lane&7) of 16-n nq tile, chunk = 2*ks + ((lane>>3)&1).
    const int lw = lane & 7;
    const uint32_t a_row_off = (uint32_t)(warp_m * 64 + (lane & 15)) * ROW_BYTES;
    const uint32_t b_row_off = (uint32_t)(warp_n * 32 + ((lane >> 4) << 3) + (lane & 7)) * ROW_BYTES;
    const int a_hi = lane >> 4;          // 0..1
    const int b_hi = (lane >> 3) & 1;    // 0..1
    uint32_t a_ck[4], b_ck[4];
#pragma unroll
    for (int ks = 0; ks < 4; ks++) {
        a_ck[ks] = (uint32_t)(((2 * ks + a_hi) ^ lw) << 4);
        b_ck[ks] = (uint32_t)(((2 * ks + b_hi) ^ lw) << 4);
    }

    for (int kt = 0; kt < KTILES; kt++) {
        CP_WAIT(1);
        __syncthreads();
        // Overwrites stage (kt+2)%3 == (kt-1)%3: all warps finished computing
        // kt-1 before passing the barrier above, so the overwrite is safe.
        if (kt + 2 < KTILES) issue_tile(sb, (kt + 2) % STAGES, kt + 2, tid, Abase, Bbase);
        CP_COMMIT();

        const int s = kt % STAGES;
        const uint32_t a_st = sb + s * STAGE_BYTES;
        const uint32_t b_st = a_st + A_STAGE_BYTES;
#pragma unroll
        for (int ks = 0; ks < 4; ks++) {   // four k16 slices per BK=64
            uint32_t af[4][4], bf[2][4];
#pragma unroll
            for (int mt = 0; mt < 4; mt++)
                LDMX4(af[mt], a_st + a_row_off + (uint32_t)(mt * 16) * ROW_BYTES + a_ck[ks]);
#pragma unroll
            for (int nq = 0; nq < 2; nq++)
                LDMX4(bf[nq], b_st + b_row_off + (uint32_t)(nq * 16) * ROW_BYTES + b_ck[ks]);
#pragma unroll
            for (int mt = 0; mt < 4; mt++)
#pragma unroll
                for (int nt = 0; nt < 4; nt++)
                    MMA_F16(acc[mt][nt], af[mt],
                            bf[nt >> 1][(nt & 1) * 2], bf[nt >> 1][(nt & 1) * 2 + 1]);
        }
    }

    // ---- epilogue: fused dequant, fp32 stores ----
    const float sin = __ldg(iscale);
    const int m_base_g = m0 + warp_m * 64;
    const int n_base_g = n0 + warp_n * 32;
#pragma unroll
    for (int nt = 0; nt < 4; nt++) {
        const int n = n_base_g + nt * 8 + 2 * (lane & 3);
        const float w0 = sin * __ldg(wscale + n);
        const float w1 = sin * __ldg(wscale + n + 1);
#pragma unroll
        for (int mt = 0; mt < 4; mt++) {
            const int r0 = m_base_g + mt * 16 + (lane >> 2);
            float2 v0, v1;
            v0.x = acc[mt][nt][0] * w0;
            v0.y = acc[mt][nt][1] * w1;
            v1.x = acc[mt][nt][2] * w0;
            v1.y = acc[mt][nt][3] * w1;
            *(float2*)(out + (size_t)r0 * N_DIM + n) = v0;
            *(float2*)(out + (size_t)(r0 + 8) * N_DIM + n) = v1;
        }
    }
}

// ---------------- launch ----------------
extern "C" void kernel_launch(void* const* d_in, const int* in_sizes, int n_in,
                              void* d_out, int out_size) {
    (void)out_size;
    // Inputs identified by element count; qweight arrives as int32.
    const float* x  = nullptr;
    const int*   w  = nullptr;
    const float* ws = nullptr;
    const float* is = nullptr;
    const long long XE = (long long)M_DIM * K_DIM;
    const long long WE = (long long)K_DIM * N_DIM;
    for (int i = 0; i < n_in; i++) {
        long long sz = in_sizes[i];
        if (sz == XE)           x  = (const float*)d_in[i];
        else if (sz == WE)      w  = (const int*)d_in[i];
        else if (sz == N_DIM)   ws = (const float*)d_in[i];
        else if (sz == 1)       is = (const float*)d_in[i];
    }
    if (!x)  x  = (const float*)d_in[0];
    if (!w)  w  = (const int*)d_in[1];
    if (!ws) ws = (const float*)d_in[2];
    if (!is) is = (const float*)d_in[3];
    float* out = (float*)d_out;

    // 1) quantize x -> fp16 ints
    size_t qthreads = (size_t)M_DIM * K_DIM / 8;
    quant_kernel<<<(unsigned)(qthreads / 256), 256>>>(x, is);

    // 2) transpose + narrow W (int32 [K,N]) -> Wt (fp16 [N,K])
    transpose_kernel<<<dim3(N_DIM / 64, K_DIM / 64), 256>>>(w);

    // 3) fp16 tensor-core GEMM + fused dequant (2 CTAs/SM)
    cudaFuncSetAttribute(gemm_kernel, cudaFuncAttributeMaxDynamicSharedMemorySize, SMEM_BYTES);
    gemm_kernel<<<(M_DIM / BM) * (N_DIM / BN), NTHREADS, SMEM_BYTES>>>(ws, is, out);
}